// round 5
// baseline (speedup 1.0000x reference)
#include <cuda_runtime.h>
#include <math.h>

#define BATCH   8192
#define OBS     21
#define HID     512
#define NL      10
#define ACT     8
#define OVERALL 5632              // HID*(NL+1)
#define IN_DIM  5653              // OBS + OVERALL
#define OUT_DIM 5640              // OVERALL + ACT

// output layout: prev_mean | log_std | new_hidden | new_mean | new_log_std
#define O_PREVMEAN  0
#define O_LOGSTD    (BATCH*ACT)
#define O_HIDDEN    (2*BATCH*ACT)
#define O_NEWMEAN   (O_HIDDEN + BATCH*OVERALL)
#define O_NEWLOGSTD (O_NEWMEAN + BATCH*ACT)

// -------- device scratch (allocation-free rule: __device__ globals) --------
__device__ float g_Wbig[NL*HID*HID];     // blocks 1..10 of W_mean, [b][n][k], k-contig
__device__ float g_W0[HID*32];           // block 0 (512 x 21) zero-padded to K=32
__device__ float g_obs_pad[BATCH*32];    // obs padded to 32 cols
__device__ float g_part[11*BATCH*ACT];   // per-segment partial sums for new_log_std

// ---------------------------------------------------------------------------
// pack: extract banded blocks into aligned layouts (run every launch; cheap)
// ---------------------------------------------------------------------------
__global__ void pack_kernel(const float* __restrict__ W_mean,
                            const float* __restrict__ obs) {
    int i = blockIdx.x * blockDim.x + threadIdx.x;
    if (i < NL*HID*HID) {
        int b   = i / (HID*HID);
        int rem = i % (HID*HID);
        int n   = rem / HID;
        int k   = rem % HID;
        // block (b+1): rows 512*(b+1)+n, cols 21+512*b+k
        g_Wbig[i] = W_mean[(size_t)(HID*(b+1)+n)*IN_DIM + OBS + HID*b + k];
        return;
    }
    int j = i - NL*HID*HID;
    if (j < HID*32) {
        int n = j >> 5, k = j & 31;
        g_W0[j] = (k < OBS) ? W_mean[(size_t)n*IN_DIM + k] : 0.0f;
        return;
    }
    int p = j - HID*32;
    if (p < BATCH*32) {
        int m = p >> 5, k = p & 31;
        g_obs_pad[p] = (k < OBS) ? obs[m*OBS + k] : 0.0f;
    }
}

// ---------------------------------------------------------------------------
// init: prev_mean copy + tanh-squashed log_std
// ---------------------------------------------------------------------------
__global__ void init_kernel(const float* __restrict__ pm,
                            const float* __restrict__ pl,
                            float* __restrict__ out) {
    int idx = blockIdx.x * blockDim.x + threadIdx.x;
    if (idx < BATCH*ACT) {
        out[O_PREVMEAN + idx] = pm[idx];
        // LOG_STD_MIN + 0.5*(LOG_STD_MAX - LOG_STD_MIN)*(tanh(x)+1)
        //   = -5 + 3.5*(tanh(x)+1) = 3.5*tanh(x) - 1.5
        out[O_LOGSTD + idx] = 3.5f * tanhf(pl[idx]) - 1.5f;
    }
}

// ---------------------------------------------------------------------------
// TF32 mma helpers
// ---------------------------------------------------------------------------
__device__ __forceinline__ unsigned f2tf(float x) {
    unsigned u;
    asm("cvt.rna.tf32.f32 %0, %1;" : "=r"(u) : "f"(x));
    return u;
}

__device__ __forceinline__ void mma8(float* c, const unsigned* a, const unsigned* b) {
    asm volatile(
        "mma.sync.aligned.m16n8k8.row.col.f32.tf32.tf32.f32 "
        "{%0,%1,%2,%3}, {%4,%5,%6,%7}, {%8,%9}, {%0,%1,%2,%3};\n"
        : "+f"(c[0]), "+f"(c[1]), "+f"(c[2]), "+f"(c[3])
        : "r"(a[0]), "r"(a[1]), "r"(a[2]), "r"(a[3]), "r"(b[0]), "r"(b[1]));
}

// ---------------------------------------------------------------------------
// main banded GEMM: new_hidden = relu(blockdiag(x @ W.T) + b)
// grid.x = 11 * 256; CTA tile 128x128, BK=16, double-buffered SMEM, TF32 MMA
// ---------------------------------------------------------------------------
__global__ __launch_bounds__(256, 2)
void gemm_kernel(const float* __restrict__ hidden0,
                 const float* __restrict__ b_mean,
                 float* __restrict__ outH) {
    const int bx    = blockIdx.x;
    const int blk   = bx >> 8;       // 0..10
    const int rr    = bx & 255;
    const int mBase = (rr >> 2) * 128;
    const int nTile = rr & 3;

    const float* Aptr; int lda; int KT;
    const float* Bptr; int ldb;
    if (blk == 0) {
        Aptr = g_obs_pad; lda = 32; KT = 2;          // K = 32 (padded 21)
        Bptr = g_W0;      ldb = 32;
    } else {
        Aptr = hidden0 + (blk - 1) * HID; lda = OVERALL; KT = 32;  // K = 512
        Bptr = g_Wbig + (size_t)(blk - 1) * HID * HID; ldb = HID;
    }
    const int colBase = blk * HID + nTile * 128;

    __shared__ unsigned As[2][128][20];   // [m][k], pad 20 -> conflict-free frags
    __shared__ unsigned Bs[2][128][20];   // [n][k]

    const int tid  = threadIdx.x;
    const int lane = tid & 31;
    const int wid  = tid >> 5;
    const int wm   = wid & 1;     // 2 warps in M (64 rows each)
    const int wn   = wid >> 1;    // 4 warps in N (32 cols each)
    const int g    = lane >> 2;
    const int tg   = lane & 3;

    // staging: 2 float4 for A, 2 for B per thread per stage
    const int m0s = tid >> 2;
    const int k0s = (tid & 3) * 4;
    const int m1s = m0s + 64;

    const float* A0 = Aptr + (size_t)(mBase + m0s) * lda + k0s;
    const float* A1 = Aptr + (size_t)(mBase + m1s) * lda + k0s;
    const float* B0 = Bptr + (size_t)(nTile * 128 + m0s) * ldb + k0s;
    const float* B1 = Bptr + (size_t)(nTile * 128 + m1s) * ldb + k0s;

    float4 ra0, ra1, rb0, rb1;

    auto fetch = [&](int kt) {
        int o = kt * 16;
        ra0 = *(const float4*)(A0 + o);
        ra1 = *(const float4*)(A1 + o);
        rb0 = *(const float4*)(B0 + o);
        rb1 = *(const float4*)(B1 + o);
    };
    auto store = [&](int buf) {
        uint4 u;
        u.x=f2tf(ra0.x); u.y=f2tf(ra0.y); u.z=f2tf(ra0.z); u.w=f2tf(ra0.w);
        *(uint4*)&As[buf][m0s][k0s] = u;
        u.x=f2tf(ra1.x); u.y=f2tf(ra1.y); u.z=f2tf(ra1.z); u.w=f2tf(ra1.w);
        *(uint4*)&As[buf][m1s][k0s] = u;
        u.x=f2tf(rb0.x); u.y=f2tf(rb0.y); u.z=f2tf(rb0.z); u.w=f2tf(rb0.w);
        *(uint4*)&Bs[buf][m0s][k0s] = u;
        u.x=f2tf(rb1.x); u.y=f2tf(rb1.y); u.z=f2tf(rb1.z); u.w=f2tf(rb1.w);
        *(uint4*)&Bs[buf][m1s][k0s] = u;
    };

    float acc[4][4][4];
    #pragma unroll
    for (int a = 0; a < 4; a++)
        #pragma unroll
        for (int b = 0; b < 4; b++)
            #pragma unroll
            for (int c = 0; c < 4; c++) acc[a][b][c] = 0.0f;

    fetch(0); store(0); __syncthreads();

    for (int kt = 0; kt < KT; kt++) {
        const int cur = kt & 1;
        if (kt + 1 < KT) fetch(kt + 1);

        #pragma unroll
        for (int k8 = 0; k8 < 2; k8++) {
            const int kk = k8 * 8;
            unsigned afr[4][4], bfr[4][2];
            #pragma unroll
            for (int mf = 0; mf < 4; mf++) {
                int ra = wm * 64 + mf * 16 + g;
                afr[mf][0] = As[cur][ra    ][kk + tg];
                afr[mf][1] = As[cur][ra + 8][kk + tg];
                afr[mf][2] = As[cur][ra    ][kk + tg + 4];
                afr[mf][3] = As[cur][ra + 8][kk + tg + 4];
            }
            #pragma unroll
            for (int nf = 0; nf < 4; nf++) {
                int cb = wn * 32 + nf * 8 + g;
                bfr[nf][0] = Bs[cur][cb][kk + tg];
                bfr[nf][1] = Bs[cur][cb][kk + tg + 4];
            }
            #pragma unroll
            for (int mf = 0; mf < 4; mf++)
                #pragma unroll
                for (int nf = 0; nf < 4; nf++)
                    mma8(acc[mf][nf], afr[mf], bfr[nf]);
        }

        if (kt + 1 < KT) store(cur ^ 1);
        __syncthreads();
    }

    // epilogue: +bias, ReLU, write new_hidden
    #pragma unroll
    for (int nf = 0; nf < 4; nf++) {
        int gc = colBase + wn * 32 + nf * 8 + 2 * tg;
        float bv0 = b_mean[gc], bv1 = b_mean[gc + 1];
        #pragma unroll
        for (int mf = 0; mf < 4; mf++) {
            int row = mBase + wm * 64 + mf * 16 + g;
            float2 v0, v1;
            v0.x = fmaxf(acc[mf][nf][0] + bv0, 0.0f);
            v0.y = fmaxf(acc[mf][nf][1] + bv1, 0.0f);
            v1.x = fmaxf(acc[mf][nf][2] + bv0, 0.0f);
            v1.y = fmaxf(acc[mf][nf][3] + bv1, 0.0f);
            *(float2*)&outH[(size_t)row * OVERALL + gc]       = v0;
            *(float2*)&outH[(size_t)(row + 8) * OVERALL + gc] = v1;
        }
    }
}

// ---------------------------------------------------------------------------
// log_std partial GEMV: per (m-chunk of 256, k-segment of 512) partial dots
// against W_logstd rows; segment 10 also produces new_mean (exact, single
// writer, deterministic). grid = (32, 11), 128 threads.
// ---------------------------------------------------------------------------
__global__ __launch_bounds__(128)
void logstd_partial_kernel(const float* __restrict__ hidden0,
                           const float* __restrict__ W_logstd,
                           const float* __restrict__ W_mean,
                           const float* __restrict__ b_mean,
                           float* __restrict__ out) {
    const int seg = blockIdx.y;          // 0..10
    const int m0  = blockIdx.x * 256;
    const int tid = threadIdx.x;
    const bool last = (seg == 10);

    __shared__ float xs[256 * 33];       // pad 33 -> conflict-free
    __shared__ float ws[256];            // W_logstd chunk [8][32]
    __shared__ float wm[256];            // W_mean (new_mean rows) chunk [8][32]

    float accL[2][8];
    float accM[2][8];
    #pragma unroll
    for (int r = 0; r < 2; r++)
        #pragma unroll
        for (int j = 0; j < 8; j++) { accL[r][j] = 0.0f; accM[r][j] = 0.0f; }

    for (int c = 0; c < 16; c++) {       // 16 chunks of 32 within the 512-seg
        __syncthreads();
        // stage x tile: 256 rows x 32 k, coalesced float4
        #pragma unroll
        for (int i = 0; i < 16; i++) {
            int f  = tid + i * 128;
            int r  = f >> 3;
            int k4 = f & 7;
            float4 v = *(const float4*)(hidden0 + (size_t)(m0 + r) * OVERALL
                                        + seg * 512 + c * 32 + k4 * 4);
            float* dst = &xs[r * 33 + k4 * 4];
            dst[0] = v.x; dst[1] = v.y; dst[2] = v.z; dst[3] = v.w;
        }
        // stage weight chunks
        #pragma unroll
        for (int i = 0; i < 2; i++) {
            int id = tid + i * 128;
            int j  = id >> 5, k = id & 31;
            ws[id] = W_logstd[(size_t)j * IN_DIM + OBS + seg * 512 + c * 32 + k];
            if (last)
                wm[id] = W_mean[(size_t)(OVERALL + j) * IN_DIM + OBS + 5120 + c * 32 + k];
        }
        __syncthreads();

        #pragma unroll
        for (int k = 0; k < 32; k++) {
            float x0 = xs[tid * 33 + k];
            float x1 = xs[(tid + 128) * 33 + k];
            #pragma unroll
            for (int j = 0; j < 8; j++) {
                float w = ws[j * 32 + k];
                accL[0][j] += x0 * w;
                accL[1][j] += x1 * w;
            }
            if (last) {
                #pragma unroll
                for (int j = 0; j < 8; j++) {
                    float w = wm[j * 32 + k];
                    accM[0][j] += x0 * w;
                    accM[1][j] += x1 * w;
                }
            }
        }
    }

    #pragma unroll
    for (int r = 0; r < 2; r++) {
        int m = m0 + tid + r * 128;
        #pragma unroll
        for (int j = 0; j < 8; j++)
            g_part[(seg * BATCH + m) * ACT + j] = accL[r][j];
        if (last) {
            #pragma unroll
            for (int j = 0; j < 8; j++)
                out[O_NEWMEAN + m * ACT + j] = accM[r][j] + b_mean[OVERALL + j];
        }
    }
}

// ---------------------------------------------------------------------------
// reduce: new_log_std = bias + obs-part + sum of 11 segment partials
// ---------------------------------------------------------------------------
__global__ void reduce_logstd_kernel(const float* __restrict__ obs,
                                     const float* __restrict__ W_logstd,
                                     const float* __restrict__ b_logstd,
                                     float* __restrict__ out) {
    int idx = blockIdx.x * blockDim.x + threadIdx.x;
    if (idx >= BATCH * ACT) return;
    int m = idx >> 3, j = idx & 7;
    float s = b_logstd[j];
    #pragma unroll
    for (int k = 0; k < OBS; k++)
        s += obs[m * OBS + k] * W_logstd[(size_t)j * IN_DIM + k];
    #pragma unroll
    for (int seg = 0; seg < 11; seg++)
        s += g_part[(seg * BATCH + m) * ACT + j];
    out[O_NEWLOGSTD + idx] = s;
}

// ---------------------------------------------------------------------------
extern "C" void kernel_launch(void* const* d_in, const int* in_sizes, int n_in,
                              void* d_out, int out_size) {
    const float* obs         = (const float*)d_in[0];
    const float* hidden0     = (const float*)d_in[1];
    const float* prev_mean   = (const float*)d_in[2];
    const float* prev_logstd = (const float*)d_in[3];
    const float* W_mean      = (const float*)d_in[4];
    const float* b_mean      = (const float*)d_in[5];
    const float* W_logstd    = (const float*)d_in[6];
    const float* b_logstd    = (const float*)d_in[7];
    float* out = (float*)d_out;

    const int pack_total = NL*HID*HID + HID*32 + BATCH*32;
    pack_kernel<<<(pack_total + 255) / 256, 256>>>(W_mean, obs);

    init_kernel<<<(BATCH*ACT + 255) / 256, 256>>>(prev_mean, prev_logstd, out);

    gemm_kernel<<<11 * 256, 256>>>(hidden0, b_mean, out + O_HIDDEN);

    dim3 gls(32, 11);
    logstd_partial_kernel<<<gls, 128>>>(hidden0, W_logstd, W_mean, b_mean, out);

    reduce_logstd_kernel<<<(BATCH*ACT + 255) / 256, 256>>>(obs, W_logstd, b_logstd, out);
}

// round 6
// speedup vs baseline: 1.0045x; 1.0045x over previous
#include <cuda_runtime.h>
#include <math.h>

#define BATCH   8192
#define OBS     21
#define HID     512
#define NL      10
#define ACT     8
#define OVERALL 5632              // HID*(NL+1)
#define IN_DIM  5653              // OBS + OVERALL
#define OUT_DIM 5640              // OVERALL + ACT

// output layout: prev_mean | log_std | new_hidden | new_mean | new_log_std
#define O_PREVMEAN  0
#define O_LOGSTD    (BATCH*ACT)
#define O_HIDDEN    (2*BATCH*ACT)
#define O_NEWMEAN   (O_HIDDEN + BATCH*OVERALL)
#define O_NEWLOGSTD (O_NEWMEAN + BATCH*ACT)

// -------- device scratch (allocation-free rule: __device__ globals) --------
__device__ float g_Wbig[NL*HID*HID];     // blocks 1..10 of W_mean, [b][n][k], k-contig
__device__ float g_W0[HID*32];           // block 0 (512 x 21) zero-padded to K=32
__device__ float g_obs_pad[BATCH*32];    // obs padded to 32 cols
__device__ float g_part[11*BATCH*ACT];   // per-segment partial sums for new_log_std

// ---------------------------------------------------------------------------
// pack: extract banded blocks into aligned layouts (run every launch; cheap)
// ---------------------------------------------------------------------------
__global__ void pack_kernel(const float* __restrict__ W_mean,
                            const float* __restrict__ obs) {
    int i = blockIdx.x * blockDim.x + threadIdx.x;
    if (i < NL*HID*HID) {
        int b   = i / (HID*HID);
        int rem = i % (HID*HID);
        int n   = rem / HID;
        int k   = rem % HID;
        // block (b+1): rows 512*(b+1)+n, cols 21+512*b+k
        g_Wbig[i] = W_mean[(size_t)(HID*(b+1)+n)*IN_DIM + OBS + HID*b + k];
        return;
    }
    int j = i - NL*HID*HID;
    if (j < HID*32) {
        int n = j >> 5, k = j & 31;
        g_W0[j] = (k < OBS) ? W_mean[(size_t)n*IN_DIM + k] : 0.0f;
        return;
    }
    int p = j - HID*32;
    if (p < BATCH*32) {
        int m = p >> 5, k = p & 31;
        g_obs_pad[p] = (k < OBS) ? obs[m*OBS + k] : 0.0f;
    }
}

// ---------------------------------------------------------------------------
// init: prev_mean copy + tanh-squashed log_std
// ---------------------------------------------------------------------------
__global__ void init_kernel(const float* __restrict__ pm,
                            const float* __restrict__ pl,
                            float* __restrict__ out) {
    int idx = blockIdx.x * blockDim.x + threadIdx.x;
    if (idx < BATCH*ACT) {
        out[O_PREVMEAN + idx] = pm[idx];
        // LOG_STD_MIN + 0.5*(LOG_STD_MAX - LOG_STD_MIN)*(tanh(x)+1)
        //   = -5 + 3.5*(tanh(x)+1) = 3.5*tanh(x) - 1.5
        out[O_LOGSTD + idx] = 3.5f * tanhf(pl[idx]) - 1.5f;
    }
}

// ---------------------------------------------------------------------------
// TF32 mma helpers
// ---------------------------------------------------------------------------
__device__ __forceinline__ unsigned f2tf(float x) {
    unsigned u;
    asm("cvt.rna.tf32.f32 %0, %1;" : "=r"(u) : "f"(x));
    return u;
}

__device__ __forceinline__ void mma8(float* c, const unsigned* a, const unsigned* b) {
    asm volatile(
        "mma.sync.aligned.m16n8k8.row.col.f32.tf32.tf32.f32 "
        "{%0,%1,%2,%3}, {%4,%5,%6,%7}, {%8,%9}, {%0,%1,%2,%3};\n"
        : "+f"(c[0]), "+f"(c[1]), "+f"(c[2]), "+f"(c[3])
        : "r"(a[0]), "r"(a[1]), "r"(a[2]), "r"(a[3]), "r"(b[0]), "r"(b[1]));
}

// ---------------------------------------------------------------------------
// main banded GEMM: new_hidden = relu(blockdiag(x @ W.T) + b)
// grid.x = 11 * 256; CTA tile 128x128, BK=16, double-buffered SMEM, TF32 MMA
// ---------------------------------------------------------------------------
__global__ __launch_bounds__(256, 2)
void gemm_kernel(const float* __restrict__ hidden0,
                 const float* __restrict__ b_mean,
                 float* __restrict__ outH) {
    const int bx    = blockIdx.x;
    const int blk   = bx >> 8;       // 0..10
    const int rr    = bx & 255;
    const int mBase = (rr >> 2) * 128;
    const int nTile = rr & 3;

    const float* Aptr; int lda; int KT;
    const float* Bptr; int ldb;
    if (blk == 0) {
        Aptr = g_obs_pad; lda = 32; KT = 2;          // K = 32 (padded 21)
        Bptr = g_W0;      ldb = 32;
    } else {
        Aptr = hidden0 + (blk - 1) * HID; lda = OVERALL; KT = 32;  // K = 512
        Bptr = g_Wbig + (size_t)(blk - 1) * HID * HID; ldb = HID;
    }
    const int colBase = blk * HID + nTile * 128;

    __shared__ unsigned As[2][128][20];   // [m][k], pad 20 -> conflict-free frags
    __shared__ unsigned Bs[2][128][20];   // [n][k]

    const int tid  = threadIdx.x;
    const int lane = tid & 31;
    const int wid  = tid >> 5;
    const int wm   = wid & 1;     // 2 warps in M (64 rows each)
    const int wn   = wid >> 1;    // 4 warps in N (32 cols each)
    const int g    = lane >> 2;
    const int tg   = lane & 3;

    // staging: 2 float4 for A, 2 for B per thread per stage
    const int m0s = tid >> 2;
    const int k0s = (tid & 3) * 4;
    const int m1s = m0s + 64;

    const float* A0 = Aptr + (size_t)(mBase + m0s) * lda + k0s;
    const float* A1 = Aptr + (size_t)(mBase + m1s) * lda + k0s;
    const float* B0 = Bptr + (size_t)(nTile * 128 + m0s) * ldb + k0s;
    const float* B1 = Bptr + (size_t)(nTile * 128 + m1s) * ldb + k0s;

    float4 ra0, ra1, rb0, rb1;

    auto fetch = [&](int kt) {
        int o = kt * 16;
        ra0 = *(const float4*)(A0 + o);
        ra1 = *(const float4*)(A1 + o);
        rb0 = *(const float4*)(B0 + o);
        rb1 = *(const float4*)(B1 + o);
    };
    auto store = [&](int buf) {
        uint4 u;
        u.x=f2tf(ra0.x); u.y=f2tf(ra0.y); u.z=f2tf(ra0.z); u.w=f2tf(ra0.w);
        *(uint4*)&As[buf][m0s][k0s] = u;
        u.x=f2tf(ra1.x); u.y=f2tf(ra1.y); u.z=f2tf(ra1.z); u.w=f2tf(ra1.w);
        *(uint4*)&As[buf][m1s][k0s] = u;
        u.x=f2tf(rb0.x); u.y=f2tf(rb0.y); u.z=f2tf(rb0.z); u.w=f2tf(rb0.w);
        *(uint4*)&Bs[buf][m0s][k0s] = u;
        u.x=f2tf(rb1.x); u.y=f2tf(rb1.y); u.z=f2tf(rb1.z); u.w=f2tf(rb1.w);
        *(uint4*)&Bs[buf][m1s][k0s] = u;
    };

    float acc[4][4][4];
    #pragma unroll
    for (int a = 0; a < 4; a++)
        #pragma unroll
        for (int b = 0; b < 4; b++)
            #pragma unroll
            for (int c = 0; c < 4; c++) acc[a][b][c] = 0.0f;

    fetch(0); store(0); __syncthreads();

    for (int kt = 0; kt < KT; kt++) {
        const int cur = kt & 1;
        if (kt + 1 < KT) fetch(kt + 1);

        #pragma unroll
        for (int k8 = 0; k8 < 2; k8++) {
            const int kk = k8 * 8;
            unsigned afr[4][4], bfr[4][2];
            #pragma unroll
            for (int mf = 0; mf < 4; mf++) {
                int ra = wm * 64 + mf * 16 + g;
                afr[mf][0] = As[cur][ra    ][kk + tg];
                afr[mf][1] = As[cur][ra + 8][kk + tg];
                afr[mf][2] = As[cur][ra    ][kk + tg + 4];
                afr[mf][3] = As[cur][ra + 8][kk + tg + 4];
            }
            #pragma unroll
            for (int nf = 0; nf < 4; nf++) {
                int cb = wn * 32 + nf * 8 + g;
                bfr[nf][0] = Bs[cur][cb][kk + tg];
                bfr[nf][1] = Bs[cur][cb][kk + tg + 4];
            }
            #pragma unroll
            for (int mf = 0; mf < 4; mf++)
                #pragma unroll
                for (int nf = 0; nf < 4; nf++)
                    mma8(acc[mf][nf], afr[mf], bfr[nf]);
        }

        if (kt + 1 < KT) store(cur ^ 1);
        __syncthreads();
    }

    // epilogue: +bias, ReLU, write new_hidden
    #pragma unroll
    for (int nf = 0; nf < 4; nf++) {
        int gc = colBase + wn * 32 + nf * 8 + 2 * tg;
        float bv0 = b_mean[gc], bv1 = b_mean[gc + 1];
        #pragma unroll
        for (int mf = 0; mf < 4; mf++) {
            int row = mBase + wm * 64 + mf * 16 + g;
            float2 v0, v1;
            v0.x = fmaxf(acc[mf][nf][0] + bv0, 0.0f);
            v0.y = fmaxf(acc[mf][nf][1] + bv1, 0.0f);
            v1.x = fmaxf(acc[mf][nf][2] + bv0, 0.0f);
            v1.y = fmaxf(acc[mf][nf][3] + bv1, 0.0f);
            *(float2*)&outH[(size_t)row * OVERALL + gc]       = v0;
            *(float2*)&outH[(size_t)(row + 8) * OVERALL + gc] = v1;
        }
    }
}

// ---------------------------------------------------------------------------
// log_std partial GEMV: per (m-chunk of 256, k-segment of 512) partial dots
// against W_logstd rows; segment 10 also produces new_mean (exact, single
// writer, deterministic). grid = (32, 11), 128 threads.
// ---------------------------------------------------------------------------
__global__ __launch_bounds__(128)
void logstd_partial_kernel(const float* __restrict__ hidden0,
                           const float* __restrict__ W_logstd,
                           const float* __restrict__ W_mean,
                           const float* __restrict__ b_mean,
                           float* __restrict__ out) {
    const int seg = blockIdx.y;          // 0..10
    const int m0  = blockIdx.x * 256;
    const int tid = threadIdx.x;
    const bool last = (seg == 10);

    __shared__ float xs[256 * 33];       // pad 33 -> conflict-free
    __shared__ float ws[256];            // W_logstd chunk [8][32]
    __shared__ float wm[256];            // W_mean (new_mean rows) chunk [8][32]

    float accL[2][8];
    float accM[2][8];
    #pragma unroll
    for (int r = 0; r < 2; r++)
        #pragma unroll
        for (int j = 0; j < 8; j++) { accL[r][j] = 0.0f; accM[r][j] = 0.0f; }

    for (int c = 0; c < 16; c++) {       // 16 chunks of 32 within the 512-seg
        __syncthreads();
        // stage x tile: 256 rows x 32 k, coalesced float4
        #pragma unroll
        for (int i = 0; i < 16; i++) {
            int f  = tid + i * 128;
            int r  = f >> 3;
            int k4 = f & 7;
            float4 v = *(const float4*)(hidden0 + (size_t)(m0 + r) * OVERALL
                                        + seg * 512 + c * 32 + k4 * 4);
            float* dst = &xs[r * 33 + k4 * 4];
            dst[0] = v.x; dst[1] = v.y; dst[2] = v.z; dst[3] = v.w;
        }
        // stage weight chunks
        #pragma unroll
        for (int i = 0; i < 2; i++) {
            int id = tid + i * 128;
            int j  = id >> 5, k = id & 31;
            ws[id] = W_logstd[(size_t)j * IN_DIM + OBS + seg * 512 + c * 32 + k];
            if (last)
                wm[id] = W_mean[(size_t)(OVERALL + j) * IN_DIM + OBS + 5120 + c * 32 + k];
        }
        __syncthreads();

        #pragma unroll
        for (int k = 0; k < 32; k++) {
            float x0 = xs[tid * 33 + k];
            float x1 = xs[(tid + 128) * 33 + k];
            #pragma unroll
            for (int j = 0; j < 8; j++) {
                float w = ws[j * 32 + k];
                accL[0][j] += x0 * w;
                accL[1][j] += x1 * w;
            }
            if (last) {
                #pragma unroll
                for (int j = 0; j < 8; j++) {
                    float w = wm[j * 32 + k];
                    accM[0][j] += x0 * w;
                    accM[1][j] += x1 * w;
                }
            }
        }
    }

    #pragma unroll
    for (int r = 0; r < 2; r++) {
        int m = m0 + tid + r * 128;
        #pragma unroll
        for (int j = 0; j < 8; j++)
            g_part[(seg * BATCH + m) * ACT + j] = accL[r][j];
        if (last) {
            #pragma unroll
            for (int j = 0; j < 8; j++)
                out[O_NEWMEAN + m * ACT + j] = accM[r][j] + b_mean[OVERALL + j];
        }
    }
}

// ---------------------------------------------------------------------------
// reduce: new_log_std = bias + obs-part + sum of 11 segment partials
// ---------------------------------------------------------------------------
__global__ void reduce_logstd_kernel(const float* __restrict__ obs,
                                     const float* __restrict__ W_logstd,
                                     const float* __restrict__ b_logstd,
                                     float* __restrict__ out) {
    int idx = blockIdx.x * blockDim.x + threadIdx.x;
    if (idx >= BATCH * ACT) return;
    int m = idx >> 3, j = idx & 7;
    float s = b_logstd[j];
    #pragma unroll
    for (int k = 0; k < OBS; k++)
        s += obs[m * OBS + k] * W_logstd[(size_t)j * IN_DIM + k];
    #pragma unroll
    for (int seg = 0; seg < 11; seg++)
        s += g_part[(seg * BATCH + m) * ACT + j];
    out[O_NEWLOGSTD + idx] = s;
}

// ---------------------------------------------------------------------------
extern "C" void kernel_launch(void* const* d_in, const int* in_sizes, int n_in,
                              void* d_out, int out_size) {
    const float* obs         = (const float*)d_in[0];
    const float* hidden0     = (const float*)d_in[1];
    const float* prev_mean   = (const float*)d_in[2];
    const float* prev_logstd = (const float*)d_in[3];
    const float* W_mean      = (const float*)d_in[4];
    const float* b_mean      = (const float*)d_in[5];
    const float* W_logstd    = (const float*)d_in[6];
    const float* b_logstd    = (const float*)d_in[7];
    float* out = (float*)d_out;

    const int pack_total = NL*HID*HID + HID*32 + BATCH*32;
    pack_kernel<<<(pack_total + 255) / 256, 256>>>(W_mean, obs);

    init_kernel<<<(BATCH*ACT + 255) / 256, 256>>>(prev_mean, prev_logstd, out);

    gemm_kernel<<<11 * 256, 256>>>(hidden0, b_mean, out + O_HIDDEN);

    dim3 gls(32, 11);
    logstd_partial_kernel<<<gls, 128>>>(hidden0, W_logstd, W_mean, b_mean, out);

    reduce_logstd_kernel<<<(BATCH*ACT + 255) / 256, 256>>>(obs, W_logstd, b_logstd, out);
}

// round 13
// speedup vs baseline: 1.1662x; 1.1609x over previous
#include <cuda_runtime.h>
#include <cuda_fp16.h>
#include <math.h>
#include <stdint.h>

#define BATCH   8192
#define OBS     21
#define HID     512
#define NL      10
#define ACT     8
#define OVERALL 5632
#define IN_DIM  5653
#define OUT_DIM 5640

#define O_PREVMEAN  0
#define O_LOGSTD    (BATCH*ACT)
#define O_HIDDEN    (2*BATCH*ACT)
#define O_NEWMEAN   (O_HIDDEN + BATCH*OVERALL)
#define O_NEWLOGSTD (O_NEWMEAN + BATCH*ACT)

// ---- device scratch (__device__ globals; no allocs) ----
__device__ __align__(16) __half g_W[NL*HID*HID];   // W blocks 1..10, [b][n][k]
__device__ __align__(16) __half g_W0[HID*32];      // block 0 (512x21 pad 32)
__device__ __align__(16) __half g_obs[BATCH*32];   // obs padded to 32
__device__ float g_part[11*BATCH*ACT];

// ---- helpers ----
__device__ __forceinline__ uint32_t smem_u32(const void* p) {
    uint32_t a;
    asm("{ .reg .u64 t; cvta.to.shared.u64 t, %1; cvt.u32.u64 %0, t; }" : "=r"(a) : "l"(p));
    return a;
}

__device__ __forceinline__ void ldsm4(unsigned& r0, unsigned& r1,
                                      unsigned& r2, unsigned& r3, uint32_t addr) {
    asm volatile("ldmatrix.sync.aligned.m8n8.x4.shared.b16 {%0,%1,%2,%3}, [%4];"
                 : "=r"(r0), "=r"(r1), "=r"(r2), "=r"(r3) : "r"(addr));
}

__device__ __forceinline__ void mma16(float* c, const unsigned* a, const unsigned* b) {
    asm volatile(
        "mma.sync.aligned.m16n8k16.row.col.f32.f16.f16.f32 "
        "{%0,%1,%2,%3}, {%4,%5,%6,%7}, {%8,%9}, {%0,%1,%2,%3};\n"
        : "+f"(c[0]), "+f"(c[1]), "+f"(c[2]), "+f"(c[3])
        : "r"(a[0]), "r"(a[1]), "r"(a[2]), "r"(a[3]), "r"(b[0]), "r"(b[1]));
}

// ---- pack: W blocks / W0 / obs -> fp16 ----
__global__ void pack_kernel(const float* __restrict__ W_mean,
                            const float* __restrict__ obs) {
    int i = blockIdx.x * blockDim.x + threadIdx.x;
    if (i < NL*HID*HID) {
        int b = i / (HID*HID), rem = i % (HID*HID);
        int n = rem / HID, k = rem % HID;
        g_W[i] = __float2half_rn(W_mean[(size_t)(HID*(b+1)+n)*IN_DIM + OBS + HID*b + k]);
        return;
    }
    int j = i - NL*HID*HID;
    if (j < HID*32) {
        int n = j >> 5, k = j & 31;
        g_W0[j] = __float2half_rn((k < OBS) ? W_mean[(size_t)n*IN_DIM + k] : 0.0f);
        return;
    }
    int p = j - HID*32;
    if (p < BATCH*32) {
        int m = p >> 5, k = p & 31;
        g_obs[p] = __float2half_rn((k < OBS) ? obs[m*OBS + k] : 0.0f);
    }
}

// ---- init: prev_mean copy + tanh-squashed log_std ----
__global__ void init_kernel(const float* __restrict__ pm,
                            const float* __restrict__ pl,
                            float* __restrict__ out) {
    int idx = blockIdx.x * blockDim.x + threadIdx.x;
    if (idx < BATCH*ACT) {
        out[O_PREVMEAN + idx] = pm[idx];
        out[O_LOGSTD + idx] = 3.5f * tanhf(pl[idx]) - 1.5f;
    }
}

// ---------------------------------------------------------------------------
// banded GEMM: new_hidden = relu(blockdiag(x @ W.T) + b)
// fp16 m16n8k16 mma + ldmatrix; CTA tile 128x128, BK=32, double-buffered
// grid = 11 * 256 (64 m-tiles x 4 n-tiles per block); 256 threads
// ---------------------------------------------------------------------------
__global__ __launch_bounds__(256, 2)
void gemm_kernel(const float* __restrict__ hidden0,
                 const float* __restrict__ b_mean,
                 float* __restrict__ outH) {
    const int bx    = blockIdx.x;
    const int blk   = bx >> 8;        // 0..10
    const int rr    = bx & 255;
    const int mBase = (rr >> 2) * 128;
    const int nTile = rr & 3;
    const int colBase = blk * HID + nTile * 128;
    const int KT = blk ? 16 : 1;      // k-iters of 32

    __shared__ __half As[2][128][40];   // stride 40 halves -> conflict-free
    __shared__ __half Bs[2][128][40];

    const int tid  = threadIdx.x;
    const int lane = tid & 31;
    const int wid  = tid >> 5;
    const int wm   = wid & 1;          // 2 warps in M (64 rows each)
    const int wn   = wid >> 1;         // 4 warps in N (32 cols each)
    const int g    = lane >> 2;
    const int tg   = lane & 3;

    // staging: thread t handles row t>>1, k-halves (t&1)*16
    const int rowS = tid >> 1;
    const int kS   = (tid & 1) * 16;

    const float* Ag = hidden0 + (size_t)(mBase + rowS) * OVERALL
                      + (blk ? (blk - 1) * 512 : 0) + kS;
    const __half* Ag0 = g_obs + (size_t)(mBase + rowS) * 32 + kS;
    const __half* Bg  = blk
        ? g_W  + ((size_t)(blk - 1) * 512 + nTile * 128 + rowS) * 512 + kS
        : g_W0 + (size_t)(nTile * 128 + rowS) * 32 + kS;

    float4 fa[4]; uint4 ha[2]; uint4 hb[2];

    auto fetch = [&](int kt) {
        if (blk) {
            const float* s = Ag + kt * 32;
            fa[0] = *(const float4*)(s);
            fa[1] = *(const float4*)(s + 4);
            fa[2] = *(const float4*)(s + 8);
            fa[3] = *(const float4*)(s + 12);
            const __half* bs = Bg + kt * 32;
            hb[0] = *(const uint4*)(bs);
            hb[1] = *(const uint4*)(bs + 8);
        } else {
            ha[0] = *(const uint4*)(Ag0);
            ha[1] = *(const uint4*)(Ag0 + 8);
            hb[0] = *(const uint4*)(Bg);
            hb[1] = *(const uint4*)(Bg + 8);
        }
    };
    auto store = [&](int buf) {
        if (blk) {
            __half2 h0 = __floats2half2_rn(fa[0].x, fa[0].y);
            __half2 h1 = __floats2half2_rn(fa[0].z, fa[0].w);
            __half2 h2 = __floats2half2_rn(fa[1].x, fa[1].y);
            __half2 h3 = __floats2half2_rn(fa[1].z, fa[1].w);
            __half2 h4 = __floats2half2_rn(fa[2].x, fa[2].y);
            __half2 h5 = __floats2half2_rn(fa[2].z, fa[2].w);
            __half2 h6 = __floats2half2_rn(fa[3].x, fa[3].y);
            __half2 h7 = __floats2half2_rn(fa[3].z, fa[3].w);
            uint4 u0, u1;
            u0.x = *(unsigned*)&h0; u0.y = *(unsigned*)&h1;
            u0.z = *(unsigned*)&h2; u0.w = *(unsigned*)&h3;
            u1.x = *(unsigned*)&h4; u1.y = *(unsigned*)&h5;
            u1.z = *(unsigned*)&h6; u1.w = *(unsigned*)&h7;
            *(uint4*)&As[buf][rowS][kS]     = u0;
            *(uint4*)&As[buf][rowS][kS + 8] = u1;
        } else {
            *(uint4*)&As[buf][rowS][kS]     = ha[0];
            *(uint4*)&As[buf][rowS][kS + 8] = ha[1];
        }
        *(uint4*)&Bs[buf][rowS][kS]     = hb[0];
        *(uint4*)&Bs[buf][rowS][kS + 8] = hb[1];
    };

    // ldmatrix per-lane address offsets (bytes)
    const uint32_t aOff = ((uint32_t)(wm*64 + (lane & 7) + ((lane >> 3) & 1) * 8) * 40
                           + (lane >> 4) * 8) * 2;
    const uint32_t bOff = ((uint32_t)(wn*32 + (lane & 7) + ((lane >> 4) & 1) * 8) * 40
                           + ((lane >> 3) & 1) * 8) * 2;
    const uint32_t aBase = smem_u32(&As[0][0][0]);
    const uint32_t bBase = smem_u32(&Bs[0][0][0]);
    const uint32_t BUFB  = 128 * 40 * 2;   // bytes per buffer

    float acc[4][4][4];
    #pragma unroll
    for (int a = 0; a < 4; a++)
        #pragma unroll
        for (int b = 0; b < 4; b++)
            #pragma unroll
            for (int c = 0; c < 4; c++) acc[a][b][c] = 0.0f;

    fetch(0); store(0); __syncthreads();

    for (int kt = 0; kt < KT; kt++) {
        const int cur = kt & 1;
        if (kt + 1 < KT) fetch(kt + 1);

        const uint32_t aA = aBase + cur * BUFB + aOff;
        const uint32_t bA = bBase + cur * BUFB + bOff;

        #pragma unroll
        for (int k16 = 0; k16 < 2; k16++) {
            const uint32_t ko = k16 * 32;   // 16 halves = 32 bytes
            unsigned af[4][4], bf[4][2];
            #pragma unroll
            for (int mt = 0; mt < 4; mt++)
                ldsm4(af[mt][0], af[mt][1], af[mt][2], af[mt][3],
                      aA + mt * (16 * 80) + ko);
            {
                unsigned r0, r1, r2, r3;
                ldsm4(r0, r1, r2, r3, bA + ko);
                bf[0][0] = r0; bf[0][1] = r1; bf[1][0] = r2; bf[1][1] = r3;
                ldsm4(r0, r1, r2, r3, bA + 16 * 80 + ko);
                bf[2][0] = r0; bf[2][1] = r1; bf[3][0] = r2; bf[3][1] = r3;
            }
            #pragma unroll
            for (int mt = 0; mt < 4; mt++)
                #pragma unroll
                for (int nt = 0; nt < 4; nt++)
                    mma16(acc[mt][nt], af[mt], bf[nt]);
        }

        if (kt + 1 < KT) store(cur ^ 1);
        __syncthreads();
    }

    // epilogue: +bias, ReLU, write new_hidden
    #pragma unroll
    for (int nt = 0; nt < 4; nt++) {
        int gc = colBase + wn * 32 + nt * 8 + 2 * tg;
        float bv0 = b_mean[gc], bv1 = b_mean[gc + 1];
        #pragma unroll
        for (int mt = 0; mt < 4; mt++) {
            int row = mBase + wm * 64 + mt * 16 + g;
            float2 v0, v1;
            v0.x = fmaxf(acc[mt][nt][0] + bv0, 0.0f);
            v0.y = fmaxf(acc[mt][nt][1] + bv1, 0.0f);
            v1.x = fmaxf(acc[mt][nt][2] + bv0, 0.0f);
            v1.y = fmaxf(acc[mt][nt][3] + bv1, 0.0f);
            *(float2*)&outH[(size_t)row * OVERALL + gc]       = v0;
            *(float2*)&outH[(size_t)(row + 8) * OVERALL + gc] = v1;
        }
    }
}

// ---- logstd partial GEMV: 256 threads, 1 row/thread, grid (32,11) ----
__global__ __launch_bounds__(256)
void logstd_partial_kernel(const float* __restrict__ hidden0,
                           const float* __restrict__ W_logstd,
                           const float* __restrict__ W_mean,
                           const float* __restrict__ b_mean,
                           float* __restrict__ out) {
    const int seg = blockIdx.y;
    const int m0  = blockIdx.x * 256;
    const int tid = threadIdx.x;
    const bool last = (seg == 10);

    __shared__ float xs[256*33];
    __shared__ float ws[256];
    __shared__ float wm[256];

    float accL[8], accM[8];
    #pragma unroll
    for (int j = 0; j < 8; j++) { accL[j] = 0.f; accM[j] = 0.f; }

    for (int c = 0; c < 16; c++) {
        __syncthreads();
        #pragma unroll
        for (int i = 0; i < 8; i++) {
            int f = tid + i*256;
            int r = f >> 3, k4 = f & 7;
            float4 v = *(const float4*)(hidden0 + (size_t)(m0 + r)*OVERALL
                                        + seg*512 + c*32 + k4*4);
            float* dst = &xs[r*33 + k4*4];
            dst[0] = v.x; dst[1] = v.y; dst[2] = v.z; dst[3] = v.w;
        }
        {
            int j = tid >> 5, k = tid & 31;
            ws[tid] = W_logstd[(size_t)j*IN_DIM + OBS + seg*512 + c*32 + k];
            if (last)
                wm[tid] = W_mean[(size_t)(OVERALL + j)*IN_DIM + OBS + 5120 + c*32 + k];
        }
        __syncthreads();

        #pragma unroll
        for (int k = 0; k < 32; k++) {
            float x0 = xs[tid*33 + k];
            #pragma unroll
            for (int j = 0; j < 8; j++) accL[j] += x0 * ws[j*32 + k];
            if (last) {
                #pragma unroll
                for (int j = 0; j < 8; j++) accM[j] += x0 * wm[j*32 + k];
            }
        }
    }

    int m = m0 + tid;
    #pragma unroll
    for (int j = 0; j < 8; j++)
        g_part[(seg*BATCH + m)*ACT + j] = accL[j];
    if (last) {
        #pragma unroll
        for (int j = 0; j < 8; j++)
            out[O_NEWMEAN + m*ACT + j] = accM[j] + b_mean[OVERALL + j];
    }
}

// ---- reduce: new_log_std = bias + obs-part + sum of 11 segment partials ----
__global__ void reduce_logstd_kernel(const float* __restrict__ obs,
                                     const float* __restrict__ W_logstd,
                                     const float* __restrict__ b_logstd,
                                     float* __restrict__ out) {
    int idx = blockIdx.x * blockDim.x + threadIdx.x;
    if (idx >= BATCH*ACT) return;
    int m = idx >> 3, j = idx & 7;
    float s = b_logstd[j];
    #pragma unroll
    for (int k = 0; k < OBS; k++)
        s += obs[m*OBS + k] * W_logstd[(size_t)j*IN_DIM + k];
    #pragma unroll
    for (int seg = 0; seg < 11; seg++)
        s += g_part[(seg*BATCH + m)*ACT + j];
    out[O_NEWLOGSTD + idx] = s;
}

// ---------------------------------------------------------------------------
extern "C" void kernel_launch(void* const* d_in, const int* in_sizes, int n_in,
                              void* d_out, int out_size) {
    const float* obs         = (const float*)d_in[0];
    const float* hidden0     = (const float*)d_in[1];
    const float* prev_mean   = (const float*)d_in[2];
    const float* prev_logstd = (const float*)d_in[3];
    const float* W_mean      = (const float*)d_in[4];
    const float* b_mean      = (const float*)d_in[5];
    const float* W_logstd    = (const float*)d_in[6];
    const float* b_logstd    = (const float*)d_in[7];
    float* out = (float*)d_out;

    const int pack_total = NL*HID*HID + HID*32 + BATCH*32;
    pack_kernel<<<(pack_total + 255) / 256, 256>>>(W_mean, obs);

    init_kernel<<<(BATCH*ACT + 255) / 256, 256>>>(prev_mean, prev_logstd, out);

    gemm_kernel<<<11 * 256, 256>>>(hidden0, b_mean, out + O_HIDDEN);

    dim3 gls(32, 11);
    logstd_partial_kernel<<<gls, 256>>>(hidden0, W_logstd, W_mean, b_mean, out);

    reduce_logstd_kernel<<<(BATCH*ACT + 255) / 256, 256>>>(obs, W_logstd, b_logstd, out);
}

// round 16
// speedup vs baseline: 1.6739x; 1.4354x over previous
#include <cuda_runtime.h>
#include <cuda_fp16.h>
#include <math.h>
#include <stdint.h>

#define BATCH   8192
#define OBS     21
#define HID     512
#define NL      10
#define ACT     8
#define OVERALL 5632
#define IN_DIM  5653
#define OUT_DIM 5640

#define O_PREVMEAN  0
#define O_LOGSTD    (BATCH*ACT)
#define O_HIDDEN    (2*BATCH*ACT)
#define O_NEWMEAN   (O_HIDDEN + BATCH*OVERALL)
#define O_NEWLOGSTD (O_NEWMEAN + BATCH*ACT)

// ---- device scratch (__device__ globals; no allocs) ----
__device__ __align__(16) __half g_W[NL*HID*HID];   // W blocks 1..10, [b][n][k]
__device__ __align__(16) __half g_W0[HID*32];      // block 0 (512x21 pad 32)
__device__ __align__(16) __half g_obs[BATCH*32];   // obs padded to 32, fp16
__device__ __align__(16) __half g_x[(size_t)BATCH*OVERALL];  // hidden0 in fp16
__device__ float g_part[11*BATCH*ACT];

// ---- helpers ----
__device__ __forceinline__ uint32_t smem_u32(const void* p) {
    uint32_t a;
    asm("{ .reg .u64 t; cvta.to.shared.u64 t, %1; cvt.u32.u64 %0, t; }" : "=r"(a) : "l"(p));
    return a;
}

__device__ __forceinline__ void ldsm4(unsigned& r0, unsigned& r1,
                                      unsigned& r2, unsigned& r3, uint32_t addr) {
    asm volatile("ldmatrix.sync.aligned.m8n8.x4.shared.b16 {%0,%1,%2,%3}, [%4];"
                 : "=r"(r0), "=r"(r1), "=r"(r2), "=r"(r3) : "r"(addr));
}

__device__ __forceinline__ void mma16(float* c, const unsigned* a, const unsigned* b) {
    asm volatile(
        "mma.sync.aligned.m16n8k16.row.col.f32.f16.f16.f32 "
        "{%0,%1,%2,%3}, {%4,%5,%6,%7}, {%8,%9}, {%0,%1,%2,%3};\n"
        : "+f"(c[0]), "+f"(c[1]), "+f"(c[2]), "+f"(c[3])
        : "r"(a[0]), "r"(a[1]), "r"(a[2]), "r"(a[3]), "r"(b[0]), "r"(b[1]));
}

#define CP_ASYNC16(dst, src) \
    asm volatile("cp.async.cg.shared.global [%0], [%1], 16;" :: "r"(dst), "l"(src))
#define CP_COMMIT() asm volatile("cp.async.commit_group;" ::: "memory")
#define CP_WAIT2()  asm volatile("cp.async.wait_group 2;" ::: "memory")

// ---- pack: W blocks / W0 / obs -> fp16 ----
__global__ void pack_kernel(const float* __restrict__ W_mean,
                            const float* __restrict__ obs) {
    int i = blockIdx.x * blockDim.x + threadIdx.x;
    if (i < NL*HID*HID) {
        int b = i / (HID*HID), rem = i % (HID*HID);
        int n = rem / HID, k = rem % HID;
        g_W[i] = __float2half_rn(W_mean[(size_t)(HID*(b+1)+n)*IN_DIM + OBS + HID*b + k]);
        return;
    }
    int j = i - NL*HID*HID;
    if (j < HID*32) {
        int n = j >> 5, k = j & 31;
        g_W0[j] = __float2half_rn((k < OBS) ? W_mean[(size_t)n*IN_DIM + k] : 0.0f);
        return;
    }
    int p = j - HID*32;
    if (p < BATCH*32) {
        int m = p >> 5, k = p & 31;
        g_obs[p] = __float2half_rn((k < OBS) ? obs[m*OBS + k] : 0.0f);
    }
}

// ---- init: prev_mean copy + tanh-squashed log_std ----
__global__ void init_kernel(const float* __restrict__ pm,
                            const float* __restrict__ pl,
                            float* __restrict__ out) {
    int idx = blockIdx.x * blockDim.x + threadIdx.x;
    if (idx < BATCH*ACT) {
        out[O_PREVMEAN + idx] = pm[idx];
        out[O_LOGSTD + idx] = 3.5f * tanhf(pl[idx]) - 1.5f;
    }
}

// ---------------------------------------------------------------------------
// logstd partial GEMV (R5 proven shape: 128 thr, 2 rows/thread, grid (32,11))
// side effect: writes g_x = fp16(hidden0) for the gemm.
// seg 10 also produces new_mean.
// ---------------------------------------------------------------------------
__global__ __launch_bounds__(128)
void logstd_partial_kernel(const float* __restrict__ hidden0,
                           const float* __restrict__ W_logstd,
                           const float* __restrict__ W_mean,
                           const float* __restrict__ b_mean,
                           float* __restrict__ out) {
    const int seg = blockIdx.y;          // 0..10
    const int m0  = blockIdx.x * 256;
    const int tid = threadIdx.x;
    const bool last = (seg == 10);

    __shared__ float xs[256 * 33];
    __shared__ float ws[256];
    __shared__ float wm[256];

    float accL[2][8];
    float accM[2][8];
    #pragma unroll
    for (int r = 0; r < 2; r++)
        #pragma unroll
        for (int j = 0; j < 8; j++) { accL[r][j] = 0.0f; accM[r][j] = 0.0f; }

    for (int c = 0; c < 16; c++) {
        __syncthreads();
        #pragma unroll
        for (int i = 0; i < 16; i++) {
            int f  = tid + i * 128;
            int r  = f >> 3;
            int k4 = f & 7;
            float4 v = *(const float4*)(hidden0 + (size_t)(m0 + r) * OVERALL
                                        + seg * 512 + c * 32 + k4 * 4);
            float* dst = &xs[r * 33 + k4 * 4];
            dst[0] = v.x; dst[1] = v.y; dst[2] = v.z; dst[3] = v.w;
            // fused fp16 conversion for the gemm's A operand
            __half2 h0 = __floats2half2_rn(v.x, v.y);
            __half2 h1 = __floats2half2_rn(v.z, v.w);
            uint2 u; u.x = *(unsigned*)&h0; u.y = *(unsigned*)&h1;
            *(uint2*)&g_x[(size_t)(m0 + r) * OVERALL + seg * 512 + c * 32 + k4 * 4] = u;
        }
        #pragma unroll
        for (int i = 0; i < 2; i++) {
            int id = tid + i * 128;
            int j  = id >> 5, k = id & 31;
            ws[id] = W_logstd[(size_t)j * IN_DIM + OBS + seg * 512 + c * 32 + k];
            if (last)
                wm[id] = W_mean[(size_t)(OVERALL + j) * IN_DIM + OBS + 5120 + c * 32 + k];
        }
        __syncthreads();

        #pragma unroll
        for (int k = 0; k < 32; k++) {
            float x0 = xs[tid * 33 + k];
            float x1 = xs[(tid + 128) * 33 + k];
            #pragma unroll
            for (int j = 0; j < 8; j++) {
                float w = ws[j * 32 + k];
                accL[0][j] += x0 * w;
                accL[1][j] += x1 * w;
            }
            if (last) {
                #pragma unroll
                for (int j = 0; j < 8; j++) {
                    float w = wm[j * 32 + k];
                    accM[0][j] += x0 * w;
                    accM[1][j] += x1 * w;
                }
            }
        }
    }

    #pragma unroll
    for (int r = 0; r < 2; r++) {
        int m = m0 + tid + r * 128;
        #pragma unroll
        for (int j = 0; j < 8; j++)
            g_part[(seg * BATCH + m) * ACT + j] = accL[r][j];
        if (last) {
            #pragma unroll
            for (int j = 0; j < 8; j++)
                out[O_NEWMEAN + m * ACT + j] = accM[r][j] + b_mean[OVERALL + j];
        }
    }
}

// ---------------------------------------------------------------------------
// banded GEMM: new_hidden = relu(blockdiag(x @ W.T) + b)
// fp16 m16n8k16 + ldmatrix; CTA tile 128x128, BK=32;
// 4-stage cp.async ring (A from g_x fp16, B from g_W fp16); 1 sync per kt.
// grid = 11*256 (64 m-tiles x 4 n-tiles per block); 256 threads
// ---------------------------------------------------------------------------
#define A_BYTES   (128*40*2)           // 10240 per operand per stage
#define STG_BYTES (2*A_BYTES)          // 20480
#define GEMM_SMEM (4*STG_BYTES)        // 81920

__global__ __launch_bounds__(256, 2)
void gemm_kernel(const float* __restrict__ b_mean,
                 float* __restrict__ outH) {
    extern __shared__ __align__(16) char smem[];
    const uint32_t sbase = smem_u32(smem);

    const int bx    = blockIdx.x;
    const int blk   = bx >> 8;        // 0..10
    const int rr    = bx & 255;
    const int mBase = (rr >> 2) * 128;
    const int nTile = rr & 3;
    const int colBase = blk * HID + nTile * 128;
    const int KT = blk ? 16 : 1;      // k-iters of 32

    const int tid  = threadIdx.x;
    const int lane = tid & 31;
    const int wid  = tid >> 5;
    const int wm   = wid & 1;          // 2 warps in M
    const int wn   = wid >> 1;         // 4 warps in N
    const int g    = lane >> 2;
    const int tg   = lane & 3;

    // cp.async chunk mapping: chunk c in [0,512): row=c>>2, k-off=(c&3)*8 halves
    auto issue = [&](int kt) {
        if (kt < KT) {
            uint32_t sl = sbase + (kt & 3) * STG_BYTES;
            #pragma unroll
            for (int i = 0; i < 2; i++) {
                int c   = tid + i * 256;
                int row = c >> 2;
                int koh = (c & 3) * 8;              // halves
                uint32_t da = sl + (uint32_t)row * 80 + (uint32_t)koh * 2;
                uint32_t db = da + A_BYTES;
                const __half *ga, *gb;
                if (blk) {
                    ga = g_x + (size_t)(mBase + row) * OVERALL
                         + (blk - 1) * 512 + kt * 32 + koh;
                    gb = g_W + ((size_t)(blk - 1) * 512 + nTile * 128 + row) * 512
                         + kt * 32 + koh;
                } else {
                    ga = g_obs + (size_t)(mBase + row) * 32 + koh;
                    gb = g_W0 + (size_t)(nTile * 128 + row) * 32 + koh;
                }
                CP_ASYNC16(da, ga);
                CP_ASYNC16(db, gb);
            }
        }
        CP_COMMIT();
    };

    issue(0); issue(1); issue(2);

    // ldmatrix per-lane byte offsets (verified in R13)
    const uint32_t aOff = ((uint32_t)(wm*64 + (lane & 7) + ((lane >> 3) & 1) * 8) * 40
                           + (lane >> 4) * 8) * 2;
    const uint32_t bOff = ((uint32_t)(wn*32 + (lane & 7) + ((lane >> 4) & 1) * 8) * 40
                           + ((lane >> 3) & 1) * 8) * 2;

    float acc[4][4][4];
    #pragma unroll
    for (int a = 0; a < 4; a++)
        #pragma unroll
        for (int b = 0; b < 4; b++)
            #pragma unroll
            for (int c = 0; c < 4; c++) acc[a][b][c] = 0.0f;

    for (int kt = 0; kt < KT; kt++) {
        CP_WAIT2();
        __syncthreads();

        const uint32_t sa = sbase + (kt & 3) * STG_BYTES + aOff;
        const uint32_t sb = sbase + (kt & 3) * STG_BYTES + A_BYTES + bOff;

        #pragma unroll
        for (int k16 = 0; k16 < 2; k16++) {
            const uint32_t ko = k16 * 32;   // 16 halves = 32 bytes
            unsigned af[4][4], bf[4][2];
            #pragma unroll
            for (int mt = 0; mt < 4; mt++)
                ldsm4(af[mt][0], af[mt][1], af[mt][2], af[mt][3],
                      sa + mt * (16 * 80) + ko);
            {
                unsigned r0, r1, r2, r3;
                ldsm4(r0, r1, r2, r3, sb + ko);
                bf[0][0] = r0; bf[0][1] = r1; bf[1][0] = r2; bf[1][1] = r3;
                ldsm4(r0, r1, r2, r3, sb + 16 * 80 + ko);
                bf[2][0] = r0; bf[2][1] = r1; bf[3][0] = r2; bf[3][1] = r3;
            }
            #pragma unroll
            for (int mt = 0; mt < 4; mt++)
                #pragma unroll
                for (int nt = 0; nt < 4; nt++)
                    mma16(acc[mt][nt], af[mt], bf[nt]);
        }

        issue(kt + 3);
    }

    // epilogue: +bias, ReLU, write new_hidden
    #pragma unroll
    for (int nt = 0; nt < 4; nt++) {
        int gc = colBase + wn * 32 + nt * 8 + 2 * tg;
        float bv0 = b_mean[gc], bv1 = b_mean[gc + 1];
        #pragma unroll
        for (int mt = 0; mt < 4; mt++) {
            int row = mBase + wm * 64 + mt * 16 + g;
            float2 v0, v1;
            v0.x = fmaxf(acc[mt][nt][0] + bv0, 0.0f);
            v0.y = fmaxf(acc[mt][nt][1] + bv1, 0.0f);
            v1.x = fmaxf(acc[mt][nt][2] + bv0, 0.0f);
            v1.y = fmaxf(acc[mt][nt][3] + bv1, 0.0f);
            *(float2*)&outH[(size_t)row * OVERALL + gc]       = v0;
            *(float2*)&outH[(size_t)(row + 8) * OVERALL + gc] = v1;
        }
    }
}

// ---- reduce: new_log_std = bias + obs-part + sum of 11 segment partials ----
__global__ void reduce_logstd_kernel(const float* __restrict__ obs,
                                     const float* __restrict__ W_logstd,
                                     const float* __restrict__ b_logstd,
                                     float* __restrict__ out) {
    int idx = blockIdx.x * blockDim.x + threadIdx.x;
    if (idx >= BATCH*ACT) return;
    int m = idx >> 3, j = idx & 7;
    float s = b_logstd[j];
    #pragma unroll
    for (int k = 0; k < OBS; k++)
        s += obs[m*OBS + k] * W_logstd[(size_t)j*IN_DIM + k];
    #pragma unroll
    for (int seg = 0; seg < 11; seg++)
        s += g_part[(seg*BATCH + m)*ACT + j];
    out[O_NEWLOGSTD + idx] = s;
}

// ---------------------------------------------------------------------------
extern "C" void kernel_launch(void* const* d_in, const int* in_sizes, int n_in,
                              void* d_out, int out_size) {
    const float* obs         = (const float*)d_in[0];
    const float* hidden0     = (const float*)d_in[1];
    const float* prev_mean   = (const float*)d_in[2];
    const float* prev_logstd = (const float*)d_in[3];
    const float* W_mean      = (const float*)d_in[4];
    const float* b_mean      = (const float*)d_in[5];
    const float* W_logstd    = (const float*)d_in[6];
    const float* b_logstd    = (const float*)d_in[7];
    float* out = (float*)d_out;

    cudaFuncSetAttribute(gemm_kernel,
                         cudaFuncAttributeMaxDynamicSharedMemorySize, GEMM_SMEM);

    const int pack_total = NL*HID*HID + HID*32 + BATCH*32;
    pack_kernel<<<(pack_total + 255) / 256, 256>>>(W_mean, obs);

    init_kernel<<<(BATCH*ACT + 255) / 256, 256>>>(prev_mean, prev_logstd, out);

    dim3 gls(32, 11);
    logstd_partial_kernel<<<gls, 128>>>(hidden0, W_logstd, W_mean, b_mean, out);

    gemm_kernel<<<11 * 256, 256, GEMM_SMEM>>>(b_mean, out + O_HIDDEN);

    reduce_logstd_kernel<<<(BATCH*ACT + 255) / 256, 256>>>(obs, W_logstd, b_logstd, out);
}